// round 7
// baseline (speedup 1.0000x reference)
#include <cuda_runtime.h>
#include <cuda_fp16.h>
#include <math.h>

// Problem constants
#define BB   16
#define TT   512
#define HH   384
#define FF   384
#define KK3  3
#define DMAX 8
#define LL   (TT * DMAX)          // 4096
#define BT   (BB * TT)            // 8192
#define KKT  (HH * KK3)           // 1152 unified reduction dim
#define H4   (HH / 4)             // 96 float4 per row
#define OUT_OFF ((size_t)BB * LL * HH)   // length[] offset in d_out

// GEMM tiling (fp16 m16n8k16): BM=128, BN=128, BK=64; 8 warps 2Mx4N, 64x32 warp tile
#define BM 128
#define BN 128
#define BK 64
#define NKT (KKT / BK)            // 18 k-iterations
#define SMEM_BYTES (2 * (BM + BN) * 16 * 8)   // 2 bufs * 256 rows * 16 uint2 = 64 KB

// Scratch (static device globals; no allocation allowed)
__device__ __half g_wt1h[FF * KKT];     // conv1 weights, f-major, pair-permuted fp16
__device__ __half g_wt2h[FF * KKT];     // conv2 weights, same layout
__device__ __half g_xh[BT * HH];        // x, fp16 + pair-permuted
__device__ float  g_h1[BT * FF];        // conv1 out (fp32)
__device__ __half g_h1h[BT * FF];       // ln_gelu(conv1) fp16 pair-permuted
__device__ float  g_h2[BT * FF];        // conv2 output (fp32)
__device__ int    g_tok[BB * LL];       // token index per expanded position (-1 = pad)

// ---------------------------------------------------------------------------
// half-index permutation: within each 16-half block, k-pairs interleaved
// [0,4,1,5,2,6,3,7] so one LDS.64 yields pairs (q, q+4) = one mma fragment.
// ---------------------------------------------------------------------------
__device__ __forceinline__ int perm8(int c) {
    int u = c & 7;
    return (c & ~7) | ((u < 4) ? (u << 1) : (((u - 4) << 1) | 1));
}
__device__ __forceinline__ int permH(int k) {
    return (perm8(k >> 1) << 1) | (k & 1);
}

// cp.async 16B with zero-fill when sz==0
__device__ __forceinline__ void cp16(void* dst, const void* src, int sz) {
    unsigned d = (unsigned)__cvta_generic_to_shared(dst);
    asm volatile("cp.async.cg.shared.global [%0], [%1], 16, %2;\n"
                 :: "r"(d), "l"(src), "r"(sz));
}

// ---------------------------------------------------------------------------
// x pre-convert: xh[m, permH(c)] = fp16(x[m, c])
// ---------------------------------------------------------------------------
__global__ void round_x_kernel(const float* __restrict__ x, __half* __restrict__ xh) {
    int i = blockIdx.x * 256 + threadIdx.x;
    int m = i / HH, c = i % HH;
    xh[m * HH + permH(c)] = __float2half_rn(x[i]);
}

// ---------------------------------------------------------------------------
// Weight transpose (both convs): w[f,c,tap] -> wt[f*1152 + tap*384 + permH(c)]
// ---------------------------------------------------------------------------
__global__ void wtrans_kernel(const float* __restrict__ w1, const float* __restrict__ w2,
                              __half* __restrict__ o1, __half* __restrict__ o2) {
    const int N = FF * HH * KK3;
    int i = blockIdx.x * 256 + threadIdx.x;
    const float* w = w1; __half* o = o1;
    int idx = i;
    if (i >= N) { idx = i - N; w = w2; o = o2; }
    int f   = idx / (HH * 3);
    int rem = idx % (HH * 3);
    int c   = rem / 3;
    int tap = rem % 3;
    o[f * KKT + tap * HH + permH(c)] = __float2half_rn(w[idx]);
}

__device__ __forceinline__ void mma_f16(float c[4], const unsigned a[4], const unsigned b[2]) {
    asm volatile(
        "mma.sync.aligned.m16n8k16.row.col.f32.f16.f16.f32 "
        "{%0,%1,%2,%3}, {%4,%5,%6,%7}, {%8,%9}, {%0,%1,%2,%3};\n"
        : "+f"(c[0]), "+f"(c[1]), "+f"(c[2]), "+f"(c[3])
        : "r"(a[0]), "r"(a[1]), "r"(a[2]), "r"(a[3]), "r"(b[0]), "r"(b[1]));
}

// ---------------------------------------------------------------------------
// Conv-as-GEMM, fp16 m16n8k16, cp.async double-buffered, 64x32 warp tiles.
// Grid (3, 64) = 192 CTAs, 256 threads, 64 KB dynamic smem.
// ---------------------------------------------------------------------------
__global__ void __launch_bounds__(256, 2) conv_gemm_kernel(
    const __half* __restrict__ Axh, const __half* __restrict__ Bwh,
    const float* __restrict__ bias, float* __restrict__ C) {
    extern __shared__ __align__(16) uint2 smem[];
    // SA[buf][m][16], SB[buf][n][16]; uint2 j (unswizzled)=4s+q holds k-pairs
    // (8s+q, 8s+q+4); swizzle j ^ ((row&3)<<2); row = 128 B.
    uint2 (*SA)[BM][16] = reinterpret_cast<uint2 (*)[BM][16]>(smem);
    uint2 (*SB)[BN][16] = reinterpret_cast<uint2 (*)[BN][16]>(smem + 2 * BM * 16);

    const int tid  = threadIdx.x;
    const int lane = tid & 31;
    const int warp = tid >> 5;
    const int m0w  = (warp & 1) * 64;     // 2 warps along M
    const int n0w  = (warp >> 1) * 32;    // 4 warps along N
    const int m0   = blockIdx.y * BM;
    const int f0   = blockIdx.x * BN;
    const int b    = m0 >> 9;
    const int t0   = m0 & (TT - 1);

    const int r = lane >> 2;
    const int q = lane & 3;

    float acc[4][4][4];
#pragma unroll
    for (int mt = 0; mt < 4; mt++)
#pragma unroll
        for (int nt = 0; nt < 4; nt++)
#pragma unroll
            for (int i = 0; i < 4; i++) acc[mt][nt][i] = 0.0f;

    // per-thread load coords: 1024 16B-chunks per tile (A and B each) -> 4/thread
    const int rr[4] = { tid >> 3, (tid + 256) >> 3, (tid + 512) >> 3, (tid + 768) >> 3 };
    const int at    = tid & 7;

#define LOAD_TILE(KT, BUF) do {                                                \
        const int kk0 = (KT) * BK;                                             \
        const int tap = kk0 / HH;                                              \
        const int c0  = kk0 - tap * HH;                                        \
        _Pragma("unroll")                                                      \
        for (int i = 0; i < 4; i++) {                                          \
            const int m    = rr[i];                                            \
            const int trow = t0 + m + tap - 1;                                 \
            const int ok   = (trow >= 0 && trow < TT);                         \
            const __half* src = Axh +                                          \
                (size_t)((b << 9) + (ok ? trow : 0)) * HH + c0 + 8 * at;       \
            cp16(&SA[BUF][m][(2 * at) ^ ((m & 3) << 2)], src, ok ? 16 : 0);    \
        }                                                                      \
        _Pragma("unroll")                                                      \
        for (int i = 0; i < 4; i++) {                                          \
            const int n = rr[i];                                               \
            const __half* src = Bwh + (size_t)(f0 + n) * KKT + kk0 + 8 * at;   \
            cp16(&SB[BUF][n][(2 * at) ^ ((n & 3) << 2)], src, 16);             \
        }                                                                      \
        asm volatile("cp.async.commit_group;\n");                              \
    } while (0)

    LOAD_TILE(0, 0);

    for (int kt = 0; kt < NKT; kt++) {
        const int cur = kt & 1;
        if (kt + 1 < NKT) {
            LOAD_TILE(kt + 1, cur ^ 1);
            asm volatile("cp.async.wait_group 1;\n");
        } else {
            asm volatile("cp.async.wait_group 0;\n");
        }
        __syncthreads();

#pragma unroll
        for (int s = 0; s < 4; s++) {       // 4 k16 steps per BK=64
            unsigned a[4][4], bf[4][2];
#pragma unroll
            for (int mt = 0; mt < 4; mt++) {
                const int mr  = m0w + mt * 16 + r;
                const int idx = ((s ^ (mr & 3)) << 2) | q;
                const uint2 va0 = SA[cur][mr][idx];
                const uint2 va1 = SA[cur][mr + 8][idx];
                a[mt][0] = va0.x; a[mt][1] = va1.x; a[mt][2] = va0.y; a[mt][3] = va1.y;
            }
#pragma unroll
            for (int nt = 0; nt < 4; nt++) {
                const int nc  = n0w + nt * 8 + r;
                const uint2 vb = SB[cur][nc][((s ^ (nc & 3)) << 2) | q];
                bf[nt][0] = vb.x; bf[nt][1] = vb.y;
            }
#pragma unroll
            for (int mt = 0; mt < 4; mt++)
#pragma unroll
                for (int nt = 0; nt < 4; nt++)
                    mma_f16(acc[mt][nt], a[mt], bf[nt]);
        }
        __syncthreads();
    }

    // epilogue: add bias (fp32), write fp32
#pragma unroll
    for (int mt = 0; mt < 4; mt++) {
        const int gm0 = m0 + m0w + mt * 16 + r;
#pragma unroll
        for (int nt = 0; nt < 4; nt++) {
            const int gf = f0 + n0w + nt * 8 + 2 * q;
            const float2 bvv = *reinterpret_cast<const float2*>(bias + gf);
            float2 o0, o1;
            o0.x = acc[mt][nt][0] + bvv.x;
            o0.y = acc[mt][nt][1] + bvv.y;
            o1.x = acc[mt][nt][2] + bvv.x;
            o1.y = acc[mt][nt][3] + bvv.y;
            *reinterpret_cast<float2*>(C + (size_t)gm0 * FF + gf) = o0;
            *reinterpret_cast<float2*>(C + (size_t)(gm0 + 8) * FF + gf) = o1;
        }
    }
#undef LOAD_TILE
}

// ---------------------------------------------------------------------------
// warp-per-row LN helpers: 12 elems per lane, shuffle-only reductions
// ---------------------------------------------------------------------------
__device__ __forceinline__ float warp_sum(float v) {
#pragma unroll
    for (int o = 16; o > 0; o >>= 1) v += __shfl_xor_sync(0xffffffffu, v, o);
    return v;
}

__device__ __forceinline__ float gelu_exact(float y) {
    return 0.5f * y * (1.0f + erff(y * 0.70710678118654752f));
}

// LayerNorm + exact GELU; reads fp32, writes fp16 pair-permuted (for conv2).
// 256 threads = 8 warps = 8 rows per block; grid BT/8.
__global__ void __launch_bounds__(256) ln_gelu_kernel(
    const float* __restrict__ h, const float* __restrict__ g, const float* __restrict__ bb,
    __half* __restrict__ oh) {
    const int row  = blockIdx.x * 8 + (threadIdx.x >> 5);
    const int lane = threadIdx.x & 31;
    const float* p = h + (size_t)row * FF;
    __half* po = oh + (size_t)row * FF;
    float v[12];
    float s = 0.0f;
#pragma unroll
    for (int i = 0; i < 12; i++) { v[i] = p[lane + 32 * i]; s += v[i]; }
    const float mu = warp_sum(s) * (1.0f / FF);
    float s2 = 0.0f;
#pragma unroll
    for (int i = 0; i < 12; i++) { v[i] -= mu; s2 += v[i] * v[i]; }
    const float rs = rsqrtf(warp_sum(s2) * (1.0f / FF) + 1e-5f);
#pragma unroll
    for (int i = 0; i < 12; i++) {
        const int c = lane + 32 * i;
        const float y = v[i] * rs * g[c] + bb[c];
        po[permH(c)] = __float2half_rn(gelu_exact(y));
    }
}

// LayerNorm + GELU + linear(384->1) + ReLU -> length[row]. warp-per-row.
__global__ void __launch_bounds__(256) ln_gelu_lin_kernel(
    const float* __restrict__ h, const float* __restrict__ g, const float* __restrict__ bb,
    const float* __restrict__ lw, const float* __restrict__ lb, float* __restrict__ lenout) {
    const int row  = blockIdx.x * 8 + (threadIdx.x >> 5);
    const int lane = threadIdx.x & 31;
    const float* p = h + (size_t)row * FF;
    float v[12];
    float s = 0.0f;
#pragma unroll
    for (int i = 0; i < 12; i++) { v[i] = p[lane + 32 * i]; s += v[i]; }
    const float mu = warp_sum(s) * (1.0f / FF);
    float s2 = 0.0f;
#pragma unroll
    for (int i = 0; i < 12; i++) { v[i] -= mu; s2 += v[i] * v[i]; }
    const float rs = rsqrtf(warp_sum(s2) * (1.0f / FF) + 1e-5f);
    float d = 0.0f;
#pragma unroll
    for (int i = 0; i < 12; i++) {
        const int c = lane + 32 * i;
        d += gelu_exact(v[i] * rs * g[c] + bb[c]) * lw[c];
    }
    const float dot = warp_sum(d);
    if (lane == 0) lenout[row] = fmaxf(dot + lb[0], 0.0f);
}

// ---------------------------------------------------------------------------
// Duration scan + token map. One block per batch, 512 threads.
// ---------------------------------------------------------------------------
__global__ void __launch_bounds__(512) build_tok_kernel(
    const float* __restrict__ td, int* __restrict__ tok) {
    __shared__ int sc[TT];
    const int b = blockIdx.x, t = threadIdx.x;
    const int d = (int)rintf(expf(td[b * TT + t]));
    sc[t] = d;
    __syncthreads();
    for (int off = 1; off < TT; off <<= 1) {
        int v = sc[t];
        int add = (t >= off) ? sc[t - off] : 0;
        __syncthreads();
        sc[t] = v + add;
        __syncthreads();
    }
    const int end = sc[t];
    const int start = end - d;
    for (int l = start; l < end; l++) tok[b * LL + l] = t;
    __syncthreads();
    const int total = sc[TT - 1];
    for (int l = total + t; l < LL; l += TT) tok[b * LL + l] = -1;
}

// ---------------------------------------------------------------------------
// Expansion: out[b,l,:] = x[b,tok[b][l],:] (or zeros). float4 per thread.
// ---------------------------------------------------------------------------
__global__ void __launch_bounds__(256) expand_kernel(
    const float* __restrict__ x, const int* __restrict__ tok, float* __restrict__ out) {
    const unsigned idx = blockIdx.x * 256u + threadIdx.x;
    const int h4 = idx % H4;
    const int l  = (idx / H4) & (LL - 1);
    const int b  = idx / (H4 * LL);
    const int t  = tok[b * LL + l];
    float4 v = make_float4(0.f, 0.f, 0.f, 0.f);
    if (t >= 0)
        v = reinterpret_cast<const float4*>(x)[(size_t)(b * TT + t) * H4 + h4];
    reinterpret_cast<float4*>(out)[idx] = v;
}

// ---------------------------------------------------------------------------
extern "C" void kernel_launch(void* const* d_in, const int* in_sizes, int n_in,
                              void* d_out, int out_size) {
    const float* x   = (const float*)d_in[0];
    const float* td  = (const float*)d_in[1];
    const float* w1  = (const float*)d_in[2];
    const float* b1  = (const float*)d_in[3];
    const float* g1  = (const float*)d_in[4];
    const float* bb1 = (const float*)d_in[5];
    const float* w2  = (const float*)d_in[6];
    const float* b2  = (const float*)d_in[7];
    const float* g2  = (const float*)d_in[8];
    const float* bb2 = (const float*)d_in[9];
    const float* lw  = (const float*)d_in[10];
    const float* lb  = (const float*)d_in[11];

    float* out = (float*)d_out;
    float* lenout = out + OUT_OFF;

    __half *wt1p, *wt2p, *xhp, *h1hp;
    float *h1p, *h2p;
    int* tokp;
    cudaGetSymbolAddress((void**)&wt1p, g_wt1h);
    cudaGetSymbolAddress((void**)&wt2p, g_wt2h);
    cudaGetSymbolAddress((void**)&xhp,  g_xh);
    cudaGetSymbolAddress((void**)&h1p,  g_h1);
    cudaGetSymbolAddress((void**)&h1hp, g_h1h);
    cudaGetSymbolAddress((void**)&h2p,  g_h2);
    cudaGetSymbolAddress((void**)&tokp, g_tok);

    cudaFuncSetAttribute(conv_gemm_kernel,
                         cudaFuncAttributeMaxDynamicSharedMemorySize, SMEM_BYTES);

    round_x_kernel<<<(BT * HH) / 256, 256>>>(x, xhp);
    wtrans_kernel<<<(2 * FF * HH * KK3) / 256, 256>>>(w1, w2, wt1p, wt2p);

    dim3 ggrid(FF / BN, BT / BM);   // (3, 64) = 192 CTAs
    conv_gemm_kernel<<<ggrid, 256, SMEM_BYTES>>>(xhp, wt1p, b1, h1p);
    ln_gelu_kernel<<<BT / 8, 256>>>(h1p, g1, bb1, h1hp);
    conv_gemm_kernel<<<ggrid, 256, SMEM_BYTES>>>(h1hp, wt2p, b2, h2p);
    ln_gelu_lin_kernel<<<BT / 8, 256>>>(h2p, g2, bb2, lw, lb, lenout);

    build_tok_kernel<<<BB, TT>>>(td, tokp);
    expand_kernel<<<(BB * LL * H4) / 256, 256>>>(x, tokp, out);
}

// round 10
// speedup vs baseline: 1.0894x; 1.0894x over previous
#include <cuda_runtime.h>
#include <cuda_fp16.h>
#include <math.h>

// Problem constants
#define BB   16
#define TT   512
#define HH   384
#define FF   384
#define KK3  3
#define DMAX 8
#define LL   (TT * DMAX)          // 4096
#define BT   (BB * TT)            // 8192
#define KKT  (HH * KK3)           // 1152 unified reduction dim
#define H4   (HH / 4)             // 96 float4 per row
#define OUT_OFF ((size_t)BB * LL * HH)   // length[] offset in d_out

// GEMM tiling (fp16: K=16 per mma, BK=64 keeps 128B smem rows) — R6 config
#define BM 128
#define BN 64
#define BK 64
#define NKT (KKT / BK)            // 18 k-iterations

// Scratch (static device globals; no allocation allowed)
__device__ __half g_wt1h[FF * KKT];     // conv1 weights, f-major, pair-permuted fp16
__device__ __half g_wt2h[FF * KKT];     // conv2 weights, same layout
__device__ __half g_xh[BT * HH];        // x, fp16 + pair-permuted
__device__ float  g_h1[BT * FF];        // conv1 out (fp32)
__device__ __half g_h1h[BT * FF];       // ln_gelu(conv1) fp16 pair-permuted
__device__ float  g_h2[BT * FF];        // conv2 output (fp32)
__device__ int    g_tok[BB * LL];       // token index per expanded position (-1 = pad)

// ---------------------------------------------------------------------------
// half-index permutation: within each 16-half block, k-pairs interleaved
// [0,4,1,5,2,6,3,7] so one LDS.64 yields pairs (q, q+4) = one mma fragment.
// ---------------------------------------------------------------------------
__device__ __forceinline__ int perm8(int c) {
    int u = c & 7;
    return (c & ~7) | ((u < 4) ? (u << 1) : (((u - 4) << 1) | 1));
}
__device__ __forceinline__ int permH(int k) {
    return (perm8(k >> 1) << 1) | (k & 1);
}

// cp.async 16B with zero-fill when sz==0
__device__ __forceinline__ void cp16(void* dst, const void* src, int sz) {
    unsigned d = (unsigned)__cvta_generic_to_shared(dst);
    asm volatile("cp.async.cg.shared.global [%0], [%1], 16, %2;\n"
                 :: "r"(d), "l"(src), "r"(sz));
}

// ---------------------------------------------------------------------------
// Merged prep: x conversion + both weight transposes in one launch.
//   i < BT*HH:             xh[m, permH(c)] = fp16(x[m, c])
//   else (two weight sets): w[f,c,tap] -> wt[f*1152 + tap*384 + permH(c)]
// ---------------------------------------------------------------------------
#define NX  (BT * HH)             // 3,145,728
#define NW  (FF * HH * KK3)       // 442,368
#define NPREP (NX + 2 * NW)       // 4,030,464 = 15744 * 256

__global__ void prep_kernel(const float* __restrict__ x, __half* __restrict__ xh,
                            const float* __restrict__ w1, const float* __restrict__ w2,
                            __half* __restrict__ o1, __half* __restrict__ o2) {
    int i = blockIdx.x * 256 + threadIdx.x;
    if (i < NX) {
        int m = i / HH, c = i % HH;
        xh[m * HH + permH(c)] = __float2half_rn(x[i]);
        return;
    }
    i -= NX;
    const float* w = w1; __half* o = o1;
    if (i >= NW) { i -= NW; w = w2; o = o2; }
    int f   = i / (HH * 3);
    int rem = i % (HH * 3);
    int c   = rem / 3;
    int tap = rem % 3;
    o[f * KKT + tap * HH + permH(c)] = __float2half_rn(w[i]);
}

__device__ __forceinline__ void mma_f16(float c[4], const unsigned a[4], const unsigned b[2]) {
    asm volatile(
        "mma.sync.aligned.m16n8k16.row.col.f32.f16.f16.f32 "
        "{%0,%1,%2,%3}, {%4,%5,%6,%7}, {%8,%9}, {%0,%1,%2,%3};\n"
        : "+f"(c[0]), "+f"(c[1]), "+f"(c[2]), "+f"(c[3])
        : "r"(a[0]), "r"(a[1]), "r"(a[2]), "r"(a[3]), "r"(b[0]), "r"(b[1]));
}

// ---------------------------------------------------------------------------
// Conv-as-GEMM, fp16 m16n8k16, cp.async double-buffered, LDS.64 fragments.
// Grid (6, 64), 256 threads (8 warps: 4M x 2N), warp tile 32x32. (R6 config)
// ---------------------------------------------------------------------------
__global__ void __launch_bounds__(256) conv_gemm_kernel(
    const __half* __restrict__ Axh, const __half* __restrict__ Bwh,
    const float* __restrict__ bias, float* __restrict__ C) {
    __shared__ __align__(16) uint2 SA[2][BM][16];   // 32 KB
    __shared__ __align__(16) uint2 SB[2][BN][16];   // 16 KB

    const int tid  = threadIdx.x;
    const int lane = tid & 31;
    const int warp = tid >> 5;
    const int m0w  = (warp & 3) * 32;
    const int n0w  = (warp >> 2) * 32;
    const int m0   = blockIdx.y * BM;
    const int f0   = blockIdx.x * BN;
    const int b    = m0 >> 9;
    const int t0   = m0 & (TT - 1);

    const int r = lane >> 2;
    const int q = lane & 3;

    float acc[2][4][4];
#pragma unroll
    for (int mt = 0; mt < 2; mt++)
#pragma unroll
        for (int nt = 0; nt < 4; nt++)
#pragma unroll
            for (int i = 0; i < 4; i++) acc[mt][nt][i] = 0.0f;

    const int amr[4] = { tid >> 3, (tid + 256) >> 3, (tid + 512) >> 3, (tid + 768) >> 3 };
    const int at     = tid & 7;
    const int bnr[2] = { tid >> 3, (tid + 256) >> 3 };

#define LOAD_TILE(KT, BUF) do {                                                \
        const int kk0 = (KT) * BK;                                             \
        const int tap = kk0 / HH;                                              \
        const int c0  = kk0 - tap * HH;                                        \
        _Pragma("unroll")                                                      \
        for (int i = 0; i < 4; i++) {                                          \
            const int m    = amr[i];                                           \
            const int trow = t0 + m + tap - 1;                                 \
            const int ok   = (trow >= 0 && trow < TT);                         \
            const __half* src = Axh +                                          \
                (size_t)((b << 9) + (ok ? trow : 0)) * HH + c0 + 8 * at;       \
            cp16(&SA[BUF][m][(2 * at) ^ ((m & 3) << 2)], src, ok ? 16 : 0);    \
        }                                                                      \
        _Pragma("unroll")                                                      \
        for (int i = 0; i < 2; i++) {                                          \
            const int n = bnr[i];                                              \
            const __half* src = Bwh + (size_t)(f0 + n) * KKT + kk0 + 8 * at;   \
            cp16(&SB[BUF][n][(2 * at) ^ ((n & 3) << 2)], src, 16);             \
        }                                                                      \
        asm volatile("cp.async.commit_group;\n");                              \
    } while (0)

    LOAD_TILE(0, 0);

    for (int kt = 0; kt < NKT; kt++) {
        const int cur = kt & 1;
        if (kt + 1 < NKT) {
            LOAD_TILE(kt + 1, cur ^ 1);
            asm volatile("cp.async.wait_group 1;\n");
        } else {
            asm volatile("cp.async.wait_group 0;\n");
        }
        __syncthreads();

#pragma unroll
        for (int s = 0; s < 4; s++) {
            unsigned a[2][4], bf[4][2];
#pragma unroll
            for (int mt = 0; mt < 2; mt++) {
                const int mr  = m0w + mt * 16 + r;
                const int idx = ((s ^ (mr & 3)) << 2) | q;
                const uint2 va0 = SA[cur][mr][idx];
                const uint2 va1 = SA[cur][mr + 8][idx];
                a[mt][0] = va0.x; a[mt][1] = va1.x; a[mt][2] = va0.y; a[mt][3] = va1.y;
            }
#pragma unroll
            for (int nt = 0; nt < 4; nt++) {
                const int nc  = n0w + nt * 8 + r;
                const uint2 vb = SB[cur][nc][((s ^ (nc & 3)) << 2) | q];
                bf[nt][0] = vb.x; bf[nt][1] = vb.y;
            }
#pragma unroll
            for (int mt = 0; mt < 2; mt++)
#pragma unroll
                for (int nt = 0; nt < 4; nt++)
                    mma_f16(acc[mt][nt], a[mt], bf[nt]);
        }
        __syncthreads();
    }

#pragma unroll
    for (int mt = 0; mt < 2; mt++) {
        const int gm0 = m0 + m0w + mt * 16 + r;
#pragma unroll
        for (int nt = 0; nt < 4; nt++) {
            const int gf = f0 + n0w + nt * 8 + 2 * q;
            const float2 bvv = *reinterpret_cast<const float2*>(bias + gf);
            float2 o0, o1;
            o0.x = acc[mt][nt][0] + bvv.x;
            o0.y = acc[mt][nt][1] + bvv.y;
            o1.x = acc[mt][nt][2] + bvv.x;
            o1.y = acc[mt][nt][3] + bvv.y;
            *reinterpret_cast<float2*>(C + (size_t)gm0 * FF + gf) = o0;
            *reinterpret_cast<float2*>(C + (size_t)(gm0 + 8) * FF + gf) = o1;
        }
    }
#undef LOAD_TILE
}

// ---------------------------------------------------------------------------
__device__ __forceinline__ float warp_sum(float v) {
#pragma unroll
    for (int o = 16; o > 0; o >>= 1) v += __shfl_xor_sync(0xffffffffu, v, o);
    return v;
}

__device__ __forceinline__ float gelu_exact(float y) {
    return 0.5f * y * (1.0f + erff(y * 0.70710678118654752f));
}

// LayerNorm + exact GELU; fp32 in, fp16 pair-permuted out. warp-per-row.
__global__ void __launch_bounds__(256) ln_gelu_kernel(
    const float* __restrict__ h, const float* __restrict__ g, const float* __restrict__ bb,
    __half* __restrict__ oh) {
    const int row  = blockIdx.x * 8 + (threadIdx.x >> 5);
    const int lane = threadIdx.x & 31;
    const float* p = h + (size_t)row * FF;
    __half* po = oh + (size_t)row * FF;
    float v[12];
    float s = 0.0f;
#pragma unroll
    for (int i = 0; i < 12; i++) { v[i] = p[lane + 32 * i]; s += v[i]; }
    const float mu = warp_sum(s) * (1.0f / FF);
    float s2 = 0.0f;
#pragma unroll
    for (int i = 0; i < 12; i++) { v[i] -= mu; s2 += v[i] * v[i]; }
    const float rs = rsqrtf(warp_sum(s2) * (1.0f / FF) + 1e-5f);
#pragma unroll
    for (int i = 0; i < 12; i++) {
        const int c = lane + 32 * i;
        po[permH(c)] = __float2half_rn(gelu_exact(v[i] * rs * g[c] + bb[c]));
    }
}

// LayerNorm + GELU + linear(384->1) + ReLU -> length[row]. warp-per-row.
__global__ void __launch_bounds__(256) ln_gelu_lin_kernel(
    const float* __restrict__ h, const float* __restrict__ g, const float* __restrict__ bb,
    const float* __restrict__ lw, const float* __restrict__ lb, float* __restrict__ lenout) {
    const int row  = blockIdx.x * 8 + (threadIdx.x >> 5);
    const int lane = threadIdx.x & 31;
    const float* p = h + (size_t)row * FF;
    float v[12];
    float s = 0.0f;
#pragma unroll
    for (int i = 0; i < 12; i++) { v[i] = p[lane + 32 * i]; s += v[i]; }
    const float mu = warp_sum(s) * (1.0f / FF);
    float s2 = 0.0f;
#pragma unroll
    for (int i = 0; i < 12; i++) { v[i] -= mu; s2 += v[i] * v[i]; }
    const float rs = rsqrtf(warp_sum(s2) * (1.0f / FF) + 1e-5f);
    float d = 0.0f;
#pragma unroll
    for (int i = 0; i < 12; i++) {
        const int c = lane + 32 * i;
        d += gelu_exact(v[i] * rs * g[c] + bb[c]) * lw[c];
    }
    const float dot = warp_sum(d);
    if (lane == 0) lenout[row] = fmaxf(dot + lb[0], 0.0f);
}

// ---------------------------------------------------------------------------
// Duration scan + token map. One block per batch, 512 threads.
// ---------------------------------------------------------------------------
__global__ void __launch_bounds__(512) build_tok_kernel(
    const float* __restrict__ td, int* __restrict__ tok) {
    __shared__ int sc[TT];
    const int b = blockIdx.x, t = threadIdx.x;
    const int d = (int)rintf(expf(td[b * TT + t]));
    sc[t] = d;
    __syncthreads();
    for (int off = 1; off < TT; off <<= 1) {
        int v = sc[t];
        int add = (t >= off) ? sc[t - off] : 0;
        __syncthreads();
        sc[t] = v + add;
        __syncthreads();
    }
    const int end = sc[t];
    const int start = end - d;
    for (int l = start; l < end; l++) tok[b * LL + l] = t;
    __syncthreads();
    const int total = sc[TT - 1];
    for (int l = total + t; l < LL; l += TT) tok[b * LL + l] = -1;
}

// ---------------------------------------------------------------------------
// Expansion: out[b,l,:] = x[b,tok[b][l],:] (or zeros). float4 per thread.
// ---------------------------------------------------------------------------
__global__ void __launch_bounds__(256) expand_kernel(
    const float* __restrict__ x, const int* __restrict__ tok, float* __restrict__ out) {
    const unsigned idx = blockIdx.x * 256u + threadIdx.x;
    const int h4 = idx % H4;
    const int l  = (idx / H4) & (LL - 1);
    const int b  = idx / (H4 * LL);
    const int t  = tok[b * LL + l];
    float4 v = make_float4(0.f, 0.f, 0.f, 0.f);
    if (t >= 0)
        v = reinterpret_cast<const float4*>(x)[(size_t)(b * TT + t) * H4 + h4];
    reinterpret_cast<float4*>(out)[idx] = v;
}

// ---------------------------------------------------------------------------
extern "C" void kernel_launch(void* const* d_in, const int* in_sizes, int n_in,
                              void* d_out, int out_size) {
    const float* x   = (const float*)d_in[0];
    const float* td  = (const float*)d_in[1];
    const float* w1  = (const float*)d_in[2];
    const float* b1  = (const float*)d_in[3];
    const float* g1  = (const float*)d_in[4];
    const float* bb1 = (const float*)d_in[5];
    const float* w2  = (const float*)d_in[6];
    const float* b2  = (const float*)d_in[7];
    const float* g2  = (const float*)d_in[8];
    const float* bb2 = (const float*)d_in[9];
    const float* lw  = (const float*)d_in[10];
    const float* lb  = (const float*)d_in[11];

    float* out = (float*)d_out;
    float* lenout = out + OUT_OFF;

    __half *wt1p, *wt2p, *xhp, *h1hp;
    float *h1p, *h2p;
    int* tokp;
    cudaGetSymbolAddress((void**)&wt1p, g_wt1h);
    cudaGetSymbolAddress((void**)&wt2p, g_wt2h);
    cudaGetSymbolAddress((void**)&xhp,  g_xh);
    cudaGetSymbolAddress((void**)&h1p,  g_h1);
    cudaGetSymbolAddress((void**)&h1hp, g_h1h);
    cudaGetSymbolAddress((void**)&h2p,  g_h2);
    cudaGetSymbolAddress((void**)&tokp, g_tok);

    // one-time side-stream + bridge events (host resources only; no device mem)
    static cudaStream_t s2 = nullptr;
    static cudaEvent_t evFork = nullptr, evJoin = nullptr;
    if (s2 == nullptr) {
        cudaStreamCreateWithFlags(&s2, cudaStreamNonBlocking);
        cudaEventCreateWithFlags(&evFork, cudaEventDisableTiming);
        cudaEventCreateWithFlags(&evJoin, cudaEventDisableTiming);
    }

    // fork: independent chain (td -> tok -> expand) on s2
    cudaEventRecord(evFork, 0);
    cudaStreamWaitEvent(s2, evFork, 0);
    build_tok_kernel<<<BB, TT, 0, s2>>>(td, tokp);
    expand_kernel<<<(BB * LL * H4) / 256, 256, 0, s2>>>(x, tokp, out);
    cudaEventRecord(evJoin, s2);

    // main chain: prep -> conv1 -> ln -> conv2 -> ln+lin
    prep_kernel<<<NPREP / 256, 256>>>(x, xhp, w1, w2, wt1p, wt2p);

    dim3 ggrid(FF / BN, BT / BM);   // (6, 64)
    conv_gemm_kernel<<<ggrid, 256>>>(xhp, wt1p, b1, h1p);
    ln_gelu_kernel<<<BT / 8, 256>>>(h1p, g1, bb1, h1hp);
    conv_gemm_kernel<<<ggrid, 256>>>(h1hp, wt2p, b2, h2p);
    ln_gelu_lin_kernel<<<BT / 8, 256>>>(h2p, g2, bb2, lw, lb, lenout);

    // join: main stream waits for the expansion branch
    cudaStreamWaitEvent(0, evJoin, 0);
}